// round 4
// baseline (speedup 1.0000x reference)
#include <cuda_runtime.h>

// Problem constants (fixed by the dataset)
#define NN 50000
#define EE 800000
#define EAX (EE + NN)   // edges + self loops

// ---------------- scratch (device globals; no allocations allowed) ----------
__device__ float g_h[(size_t)NN * 256];   // per-layer transformed features [N, H*C]
__device__ float g_y[(size_t)NN * 64];    // layer-1 output [N, 64]
__device__ float g_a[(size_t)NN * 8];     // [N][0..3]=a_src per head, [4..7]=a_dst per head
__device__ int   g_counts[NN];
__device__ int   g_cursor[NN];
__device__ int   g_offsets[NN + 1];
__device__ int   g_csrc[EAX];             // CSR (by dst): source node ids
__device__ int   g_is64;                  // edge_index dtype flag (1 = int64)

// ---------------------------------------------------------------------------
// Detect whether edge_index was materialized as int64 or int32.
// int32 data misread as int64 packs two random ids -> value >= 2^32 almost
// surely within 256 samples. Genuine int64 ids are all in [0, N).
// ---------------------------------------------------------------------------
__global__ void detect_kernel(const void* __restrict__ ei, int Nn, int E) {
    if (threadIdx.x != 0 || blockIdx.x != 0) return;
    const long long* p = (const long long*)ei;
    int ns = (E < 256) ? E : 256;
    int ok64 = 1;
    for (int i = 0; i < ns; i++) {
        long long v = p[i];
        if (v < 0 || v >= (long long)Nn) { ok64 = 0; break; }
    }
    g_is64 = ok64;
}

__device__ __forceinline__ int edge_at(const void* ei, long long idx) {
    return g_is64 ? (int)((const long long*)ei)[idx]
                  : ((const int*)ei)[idx];
}

// ---------------------------------------------------------------------------
// GEMM: X[M,K] @ W[K,256] -> g_h[M,256].  W is L2-resident (<=128KB).
// Block: 256 threads; tile 32 rows x 256 cols; thread t owns column t.
// ---------------------------------------------------------------------------
template <int K, bool FROM_Y>
__global__ void __launch_bounds__(256) gemm_kernel(const float* __restrict__ Xin,
                                                   const float* __restrict__ W, int M) {
    __shared__ float xs[32 * K];
    const float* X = FROM_Y ? g_y : Xin;
    int row0 = blockIdx.x * 32;
    int col  = threadIdx.x;  // 0..255

    for (int idx = threadIdx.x; idx < 32 * K; idx += 256) {
        int r = idx / K, c = idx - r * K;
        int gr = row0 + r;
        xs[idx] = (gr < M) ? X[(size_t)gr * K + c] : 0.f;
    }
    __syncthreads();

    float out[32];
#pragma unroll
    for (int r = 0; r < 32; r++) out[r] = 0.f;

#pragma unroll 4
    for (int k = 0; k < K; k++) {
        float w = __ldg(&W[k * 256 + col]);
#pragma unroll
        for (int r = 0; r < 32; r++)
            out[r] = fmaf(xs[r * K + k], w, out[r]);
    }

#pragma unroll 4
    for (int r = 0; r < 32; r++) {
        int gr = row0 + r;
        if (gr < M) g_h[(size_t)gr * 256 + col] = out[r];
    }
}

// ---------------------------------------------------------------------------
// Per-node attention coefficients: a_src[n,h], a_dst[n,h].  One warp/node.
// ---------------------------------------------------------------------------
__global__ void __launch_bounds__(256) attn_kernel(const float* __restrict__ att_src,
                                                   const float* __restrict__ att_dst, int Nn) {
    int warp = (blockIdx.x * blockDim.x + threadIdx.x) >> 5;
    int lane = threadIdx.x & 31;
    if (warp >= Nn) return;
    const float* hr = g_h + (size_t)warp * 256;
#pragma unroll
    for (int hh = 0; hh < 4; hh++) {
        float v0 = hr[hh * 64 + lane];
        float v1 = hr[hh * 64 + 32 + lane];
        float ps = v0 * att_src[hh * 64 + lane] + v1 * att_src[hh * 64 + 32 + lane];
        float pd = v0 * att_dst[hh * 64 + lane] + v1 * att_dst[hh * 64 + 32 + lane];
#pragma unroll
        for (int off = 16; off; off >>= 1) {
            ps += __shfl_xor_sync(0xffffffffu, ps, off);
            pd += __shfl_xor_sync(0xffffffffu, pd, off);
        }
        if (lane == 0) {
            g_a[(size_t)warp * 8 + hh]     = ps;
            g_a[(size_t)warp * 8 + 4 + hh] = pd;
        }
    }
}

// ---------------------------- CSR build ------------------------------------
__global__ void zero_kernel(int Nn) {
    int t = blockIdx.x * blockDim.x + threadIdx.x;
    if (t < Nn) { g_counts[t] = 0; g_cursor[t] = 0; }
}

__global__ void count_kernel(const void* __restrict__ ei, int E, int Nn) {
    int t = blockIdx.x * blockDim.x + threadIdx.x;
    if (t >= E + Nn) return;
    int d = (t < E) ? edge_at(ei, (long long)E + t) : (t - E);
    atomicAdd(&g_counts[d], 1);
}

// Single-block exclusive scan over counts -> offsets (N ~ 50K, trivial cost)
__global__ void scan_kernel(int n) {
    __shared__ int sh[1024];
    __shared__ int carry;
    int tid = threadIdx.x;
    if (tid == 0) { carry = 0; g_offsets[0] = 0; }
    __syncthreads();
    for (int base = 0; base < n; base += 1024) {
        int i = base + tid;
        int v = (i < n) ? g_counts[i] : 0;
        sh[tid] = v;
        __syncthreads();
        for (int off = 1; off < 1024; off <<= 1) {
            int t = (tid >= off) ? sh[tid - off] : 0;
            __syncthreads();
            sh[tid] += t;
            __syncthreads();
        }
        int incl = sh[tid] + carry;
        if (i < n) g_offsets[i + 1] = incl;
        __syncthreads();
        if (tid == 1023) carry = incl;
        __syncthreads();
    }
}

__global__ void scatter_kernel(const void* __restrict__ ei, int E, int Nn) {
    int t = blockIdx.x * blockDim.x + threadIdx.x;
    if (t >= E + Nn) return;
    int s, d;
    if (t < E) { s = edge_at(ei, t); d = edge_at(ei, (long long)E + t); }
    else       { s = d = t - E; }
    int pos = atomicAdd(&g_cursor[d], 1);
    g_csrc[g_offsets[d] + pos] = s;
}

// ---------------------------------------------------------------------------
// GAT aggregation: one warp per destination node.
// Pass 1: per-head max over incoming edges (lane-parallel over edges).
// Pass 2: whole-warp per edge: w=exp(e-m), accumulate w * h[src] into
//         8 regs/lane; normalize, head-mean, +bias, optional ReLU.
// Lane l, reg i covers element (head = i>>1, col = (i&1)*32 + l).
// ---------------------------------------------------------------------------
template <bool RELU, bool TO_Y>
__global__ void __launch_bounds__(256) gat_aggregate(const float* __restrict__ bias,
                                                     float* __restrict__ outp, int Nn) {
    int warp = (blockIdx.x * blockDim.x + threadIdx.x) >> 5;
    int lane = threadIdx.x & 31;
    if (warp >= Nn) return;
    int n   = warp;
    int beg = g_offsets[n], end = g_offsets[n + 1];

    float adst[4];
#pragma unroll
    for (int hh = 0; hh < 4; hh++) adst[hh] = g_a[(size_t)n * 8 + 4 + hh];

    // pass 1: per-head max
    float m[4] = {-3.4e38f, -3.4e38f, -3.4e38f, -3.4e38f};
    for (int j = beg + lane; j < end; j += 32) {
        int s = g_csrc[j];
#pragma unroll
        for (int hh = 0; hh < 4; hh++) {
            float e = g_a[(size_t)s * 8 + hh] + adst[hh];
            e = (e > 0.f) ? e : 0.2f * e;
            m[hh] = fmaxf(m[hh], e);
        }
    }
#pragma unroll
    for (int off = 16; off; off >>= 1) {
#pragma unroll
        for (int hh = 0; hh < 4; hh++)
            m[hh] = fmaxf(m[hh], __shfl_xor_sync(0xffffffffu, m[hh], off));
    }

    // pass 2: weighted accumulate
    float acc[8];
#pragma unroll
    for (int i = 0; i < 8; i++) acc[i] = 0.f;
    float ssum[4] = {0.f, 0.f, 0.f, 0.f};

    for (int j = beg; j < end; j++) {
        int s = g_csrc[j];  // uniform across warp -> broadcast
        float w[4];
#pragma unroll
        for (int hh = 0; hh < 4; hh++) {
            float e = g_a[(size_t)s * 8 + hh] + adst[hh];
            e = (e > 0.f) ? e : 0.2f * e;
            w[hh] = __expf(e - m[hh]);
            ssum[hh] += w[hh];
        }
        const float* hr = g_h + (size_t)s * 256 + lane;
#pragma unroll
        for (int i = 0; i < 8; i++)
            acc[i] = fmaf(hr[32 * i], w[i >> 1], acc[i]);
    }

#pragma unroll
    for (int i = 0; i < 8; i++) acc[i] /= (ssum[i >> 1] + 1e-16f);

    float y0 = 0.25f * (acc[0] + acc[2] + acc[4] + acc[6]) + bias[lane];
    float y1 = 0.25f * (acc[1] + acc[3] + acc[5] + acc[7]) + bias[32 + lane];
    if (RELU) { y0 = fmaxf(y0, 0.f); y1 = fmaxf(y1, 0.f); }

    float* out = TO_Y ? g_y : outp;
    out[(size_t)n * 64 + lane]      = y0;
    out[(size_t)n * 64 + 32 + lane] = y1;
}

// ---------------------------------------------------------------------------
extern "C" void kernel_launch(void* const* d_in, const int* in_sizes, int n_in,
                              void* d_out, int out_size) {
    const float* x   = (const float*)d_in[0];
    const void*  ei  = d_in[1];
    const float* W1  = (const float*)d_in[2];
    const float* as1 = (const float*)d_in[3];
    const float* ad1 = (const float*)d_in[4];
    const float* b1  = (const float*)d_in[5];
    const float* W2  = (const float*)d_in[6];
    const float* as2 = (const float*)d_in[7];
    const float* ad2 = (const float*)d_in[8];
    const float* b2  = (const float*)d_in[9];

    int N  = in_sizes[0] / 128;
    int E  = in_sizes[1] / 2;
    int EA = E + N;

    // ---- edge dtype detection + CSR build (same graph for both layers) ----
    detect_kernel<<<1, 1>>>(ei, N, E);
    zero_kernel<<<(N + 255) / 256, 256>>>(N);
    count_kernel<<<(EA + 255) / 256, 256>>>(ei, E, N);
    scan_kernel<<<1, 1024>>>(N);
    scatter_kernel<<<(EA + 255) / 256, 256>>>(ei, E, N);

    int nodeWarpBlocks = (N + 7) / 8;   // 256 thr = 8 warps/block

    // ---- layer 1 ----
    gemm_kernel<128, false><<<(N + 31) / 32, 256>>>(x, W1, N);
    attn_kernel<<<nodeWarpBlocks, 256>>>(as1, ad1, N);
    gat_aggregate<true, true><<<nodeWarpBlocks, 256>>>(b1, nullptr, N);

    // ---- layer 2 ----
    gemm_kernel<64, true><<<(N + 31) / 32, 256>>>(nullptr, W2, N);
    attn_kernel<<<nodeWarpBlocks, 256>>>(as2, ad2, N);
    gat_aggregate<false, false><<<nodeWarpBlocks, 256>>>(b2, (float*)d_out, N);
}

// round 5
// speedup vs baseline: 1.2501x; 1.2501x over previous
#include <cuda_runtime.h>

// Problem constants (fixed by the dataset)
#define NN 50000
#define EE 800000
#define EAX (EE + NN)   // edges + self loops

// ---------------- scratch (device globals; no allocations allowed) ----------
__device__ float g_h[(size_t)NN * 256];   // per-layer transformed features [N, H*C]
__device__ float g_y[(size_t)NN * 64];    // layer-1 output [N, 64]
__device__ float g_a[(size_t)NN * 8];     // [N][0..3]=a_src per head, [4..7]=a_dst per head
__device__ int   g_counts[NN];
__device__ int   g_cursor[NN];
__device__ int   g_off[NN];               // CSR begin per dst (order run-varying, values consistent)
__device__ int   g_csrc[EAX];             // CSR (by dst): source node ids
__device__ int   g_total;
__device__ int   g_is64;                  // edge_index dtype flag (1 = int64)

// ---------------------------------------------------------------------------
// Detect whether edge_index was materialized as int64 or int32.
// ---------------------------------------------------------------------------
__global__ void detect_kernel(const void* __restrict__ ei, int Nn, int E) {
    if (threadIdx.x != 0 || blockIdx.x != 0) return;
    const long long* p = (const long long*)ei;
    int ns = (E < 256) ? E : 256;
    int ok64 = 1;
    for (int i = 0; i < ns; i++) {
        long long v = p[i];
        if (v < 0 || v >= (long long)Nn) { ok64 = 0; break; }
    }
    g_is64 = ok64;
}

__device__ __forceinline__ int edge_at(const void* ei, long long idx) {
    return g_is64 ? (int)((const long long*)ei)[idx]
                  : ((const int*)ei)[idx];
}

// ---------------------------------------------------------------------------
// GEMM: X[M,K] @ W[K,256] -> g_h[M,256].  W is L2-resident.
// Block: 256 threads; tile 32 rows x 256 cols; thread t owns column t.
// ---------------------------------------------------------------------------
template <int K, bool FROM_Y>
__global__ void __launch_bounds__(256) gemm_kernel(const float* __restrict__ Xin,
                                                   const float* __restrict__ W, int M) {
    __shared__ float xs[32 * K];
    const float* X = FROM_Y ? g_y : Xin;
    int row0 = blockIdx.x * 32;
    int col  = threadIdx.x;  // 0..255

    for (int idx = threadIdx.x; idx < 32 * K; idx += 256) {
        int r = idx / K, c = idx - r * K;
        int gr = row0 + r;
        xs[idx] = (gr < M) ? X[(size_t)gr * K + c] : 0.f;
    }
    __syncthreads();

    float out[32];
#pragma unroll
    for (int r = 0; r < 32; r++) out[r] = 0.f;

#pragma unroll 4
    for (int k = 0; k < K; k++) {
        float w = __ldg(&W[k * 256 + col]);
#pragma unroll
        for (int r = 0; r < 32; r++)
            out[r] = fmaf(xs[r * K + k], w, out[r]);
    }

#pragma unroll 4
    for (int r = 0; r < 32; r++) {
        int gr = row0 + r;
        if (gr < M) g_h[(size_t)gr * 256 + col] = out[r];
    }
}

// ---------------------------------------------------------------------------
// Per-node attention coefficients: a_src[n,h] (slots 0..3), a_dst (4..7).
// One warp per node.
// ---------------------------------------------------------------------------
__global__ void __launch_bounds__(256) attn_kernel(const float* __restrict__ att_src,
                                                   const float* __restrict__ att_dst, int Nn) {
    int warp = (blockIdx.x * blockDim.x + threadIdx.x) >> 5;
    int lane = threadIdx.x & 31;
    if (warp >= Nn) return;
    const float* hr = g_h + (size_t)warp * 256;
#pragma unroll
    for (int hh = 0; hh < 4; hh++) {
        float v0 = hr[hh * 64 + lane];
        float v1 = hr[hh * 64 + 32 + lane];
        float ps = v0 * att_src[hh * 64 + lane] + v1 * att_src[hh * 64 + 32 + lane];
        float pd = v0 * att_dst[hh * 64 + lane] + v1 * att_dst[hh * 64 + 32 + lane];
#pragma unroll
        for (int off = 16; off; off >>= 1) {
            ps += __shfl_xor_sync(0xffffffffu, ps, off);
            pd += __shfl_xor_sync(0xffffffffu, pd, off);
        }
        if (lane == 0) {
            g_a[(size_t)warp * 8 + hh]     = ps;
            g_a[(size_t)warp * 8 + 4 + hh] = pd;
        }
    }
}

// ---------------------------- CSR build ------------------------------------
__global__ void zero_kernel(int Nn) {
    int t = blockIdx.x * blockDim.x + threadIdx.x;
    if (t < Nn) { g_counts[t] = 0; g_cursor[t] = 0; }
    if (t == 0) g_total = 0;
}

__global__ void count_kernel(const void* __restrict__ ei, int E, int Nn) {
    int t = blockIdx.x * blockDim.x + threadIdx.x;
    if (t >= E + Nn) return;
    int d = (t < E) ? edge_at(ei, (long long)E + t) : (t - E);
    atomicAdd(&g_counts[d], 1);
}

// Device-wide offset assignment: warp shfl-scan + one atomicAdd per warp.
// Slot blocks are assigned in arrival order (run-varying), which is fine:
// only per-node [beg, beg+count) consistency is required.
__global__ void offsets_kernel(int Nn) {
    int t    = blockIdx.x * blockDim.x + threadIdx.x;
    int lane = threadIdx.x & 31;
    int c    = (t < Nn) ? g_counts[t] : 0;
    int incl = c;
#pragma unroll
    for (int off = 1; off < 32; off <<= 1) {
        int v = __shfl_up_sync(0xffffffffu, incl, off);
        if (lane >= off) incl += v;
    }
    int tot = __shfl_sync(0xffffffffu, incl, 31);
    int base = 0;
    if (lane == 31) base = atomicAdd(&g_total, tot);
    base = __shfl_sync(0xffffffffu, base, 31);
    if (t < Nn) g_off[t] = base + incl - c;
}

__global__ void scatter_kernel(const void* __restrict__ ei, int E, int Nn) {
    int t = blockIdx.x * blockDim.x + threadIdx.x;
    if (t >= E + Nn) return;
    int s, d;
    if (t < E) { s = edge_at(ei, t); d = edge_at(ei, (long long)E + t); }
    else       { s = d = t - E; }
    int pos = atomicAdd(&g_cursor[d], 1);
    g_csrc[g_off[d] + pos] = s;
}

// ---------------------------------------------------------------------------
// GAT aggregation, single pass (no max subtraction: |e| <= ~6, exp is safe
// and alpha is mathematically identical to the max-shifted form).
// One warp per destination node. Lane l owns columns l*4..l*4+3 of head
// pair {l/16, l/16+2}; head mean via shfl_xor(16); lanes 0-15 store float4.
// ---------------------------------------------------------------------------
template <bool RELU, bool TO_Y>
__global__ void __launch_bounds__(256) gat_aggregate(const float* __restrict__ bias,
                                                     float* __restrict__ outp, int Nn) {
    int warp = (blockIdx.x * blockDim.x + threadIdx.x) >> 5;
    int lane = threadIdx.x & 31;
    if (warp >= Nn) return;
    int n   = warp;
    int beg = g_off[n];
    int cnt = g_counts[n];

    float4 ad4 = *(const float4*)(g_a + (size_t)n * 8 + 4);

    float4 acc0 = {0.f, 0.f, 0.f, 0.f};
    float4 acc1 = {0.f, 0.f, 0.f, 0.f};
    float  s0 = 0.f, s1 = 0.f, s2 = 0.f, s3 = 0.f;
    int    hlo = lane >> 4;          // 0 or 1

    for (int j = 0; j < cnt; j++) {
        int s = g_csrc[beg + j];                             // warp-uniform
        float4 as4 = *(const float4*)(g_a + (size_t)s * 8);  // broadcast 16B

        float e0 = as4.x + ad4.x; e0 = (e0 > 0.f) ? e0 : 0.2f * e0;
        float e1 = as4.y + ad4.y; e1 = (e1 > 0.f) ? e1 : 0.2f * e1;
        float e2 = as4.z + ad4.z; e2 = (e2 > 0.f) ? e2 : 0.2f * e2;
        float e3 = as4.w + ad4.w; e3 = (e3 > 0.f) ? e3 : 0.2f * e3;
        float w0 = __expf(e0), w1 = __expf(e1), w2 = __expf(e2), w3 = __expf(e3);
        s0 += w0; s1 += w1; s2 += w2; s3 += w3;

        float wlo = hlo ? w1 : w0;
        float whi = hlo ? w3 : w2;

        const float4* hr = (const float4*)(g_h + (size_t)s * 256);
        float4 v0 = hr[lane];        // cols lane*4..+3        (heads 0/1)
        float4 v1 = hr[32 + lane];   // cols 128+lane*4..+3    (heads 2/3)

        acc0.x = fmaf(wlo, v0.x, acc0.x); acc0.y = fmaf(wlo, v0.y, acc0.y);
        acc0.z = fmaf(wlo, v0.z, acc0.z); acc0.w = fmaf(wlo, v0.w, acc0.w);
        acc1.x = fmaf(whi, v1.x, acc1.x); acc1.y = fmaf(whi, v1.y, acc1.y);
        acc1.z = fmaf(whi, v1.z, acc1.z); acc1.w = fmaf(whi, v1.w, acc1.w);
    }

    float slo = (hlo ? s1 : s0) + 1e-16f;
    float shi = (hlo ? s3 : s2) + 1e-16f;
    float rlo = 1.f / slo, rhi = 1.f / shi;

    // per-head normalize, then sum this lane's two heads
    float tx = acc0.x * rlo + acc1.x * rhi;
    float ty = acc0.y * rlo + acc1.y * rhi;
    float tz = acc0.z * rlo + acc1.z * rhi;
    float tw = acc0.w * rlo + acc1.w * rhi;

    // add partner lane's head pair (lanes l and l^16 cover same columns)
    tx += __shfl_xor_sync(0xffffffffu, tx, 16);
    ty += __shfl_xor_sync(0xffffffffu, ty, 16);
    tz += __shfl_xor_sync(0xffffffffu, tz, 16);
    tw += __shfl_xor_sync(0xffffffffu, tw, 16);

    if (lane < 16) {
        int c0 = lane * 4;
        float4 b4 = *(const float4*)(bias + c0);
        float4 r;
        r.x = 0.25f * tx + b4.x;
        r.y = 0.25f * ty + b4.y;
        r.z = 0.25f * tz + b4.z;
        r.w = 0.25f * tw + b4.w;
        if (RELU) {
            r.x = fmaxf(r.x, 0.f); r.y = fmaxf(r.y, 0.f);
            r.z = fmaxf(r.z, 0.f); r.w = fmaxf(r.w, 0.f);
        }
        float* out = TO_Y ? g_y : outp;
        *(float4*)(out + (size_t)n * 64 + c0) = r;
    }
}

// ---------------------------------------------------------------------------
extern "C" void kernel_launch(void* const* d_in, const int* in_sizes, int n_in,
                              void* d_out, int out_size) {
    const float* x   = (const float*)d_in[0];
    const void*  ei  = d_in[1];
    const float* W1  = (const float*)d_in[2];
    const float* as1 = (const float*)d_in[3];
    const float* ad1 = (const float*)d_in[4];
    const float* b1  = (const float*)d_in[5];
    const float* W2  = (const float*)d_in[6];
    const float* as2 = (const float*)d_in[7];
    const float* ad2 = (const float*)d_in[8];
    const float* b2  = (const float*)d_in[9];

    int N  = in_sizes[0] / 128;
    int E  = in_sizes[1] / 2;
    int EA = E + N;

    // ---- edge dtype detection + CSR build (same graph for both layers) ----
    detect_kernel<<<1, 1>>>(ei, N, E);
    zero_kernel<<<(N + 255) / 256, 256>>>(N);
    count_kernel<<<(EA + 255) / 256, 256>>>(ei, E, N);
    offsets_kernel<<<(N + 255) / 256, 256>>>(N);
    scatter_kernel<<<(EA + 255) / 256, 256>>>(ei, E, N);

    int nodeWarpBlocks = (N + 7) / 8;   // 256 thr = 8 warps/block

    // ---- layer 1 ----
    gemm_kernel<128, false><<<(N + 31) / 32, 256>>>(x, W1, N);
    attn_kernel<<<nodeWarpBlocks, 256>>>(as1, ad1, N);
    gat_aggregate<true, true><<<nodeWarpBlocks, 256>>>(b1, nullptr, N);

    // ---- layer 2 ----
    gemm_kernel<64, true><<<(N + 31) / 32, 256>>>(nullptr, W2, N);
    attn_kernel<<<nodeWarpBlocks, 256>>>(as2, ad2, N);
    gat_aggregate<false, false><<<nodeWarpBlocks, 256>>>(b2, (float*)d_out, N);
}

// round 6
// speedup vs baseline: 1.3156x; 1.0524x over previous
#include <cuda_runtime.h>
#include <cuda_fp16.h>

// Problem constants (fixed by the dataset)
#define NN 50000
#define EE 800000
#define EAX (EE + NN)   // edges + self loops

// ---------------- scratch (device globals; no allocations allowed) ----------
__device__ float  g_h[(size_t)NN * 256];   // fp32 features (read by attn)
__device__ __half g_hh[(size_t)NN * 256];  // fp16 features (read by aggregate)
__device__ float  g_y[(size_t)NN * 64];    // layer-1 output [N, 64]
__device__ float  g_a[(size_t)NN * 8];     // [0..3]=a_src, [4..7]=a_dst per head
__device__ int    g_counts[NN];
__device__ int    g_cursor[NN];
__device__ int    g_off[NN];               // CSR begin per dst (slot order run-varying)
__device__ int    g_csrc[EAX];             // CSR (by dst): source node ids
__device__ int    g_total;
__device__ int    g_is64;                  // edge_index dtype flag (1 = int64)

// ---------------------------------------------------------------------------
__global__ void detect_kernel(const void* __restrict__ ei, int Nn, int E) {
    if (threadIdx.x != 0 || blockIdx.x != 0) return;
    const long long* p = (const long long*)ei;
    int ns = (E < 256) ? E : 256;
    int ok64 = 1;
    for (int i = 0; i < ns; i++) {
        long long v = p[i];
        if (v < 0 || v >= (long long)Nn) { ok64 = 0; break; }
    }
    g_is64 = ok64;
}

__device__ __forceinline__ int edge_at(const void* ei, long long idx) {
    return g_is64 ? (int)((const long long*)ei)[idx]
                  : ((const int*)ei)[idx];
}

// ---------------------------------------------------------------------------
// GEMM: X[M,K] @ W[K,256] -> g_h (fp32) + g_hh (fp16).  W is L2-resident.
// Block: 256 threads; tile 32 rows x 256 cols; thread t owns column t.
// ---------------------------------------------------------------------------
template <int K, bool FROM_Y>
__global__ void __launch_bounds__(256) gemm_kernel(const float* __restrict__ Xin,
                                                   const float* __restrict__ W, int M) {
    __shared__ float xs[32 * K];
    const float* X = FROM_Y ? g_y : Xin;
    int row0 = blockIdx.x * 32;
    int col  = threadIdx.x;  // 0..255

    for (int idx = threadIdx.x; idx < 32 * K; idx += 256) {
        int r = idx / K, c = idx - r * K;
        int gr = row0 + r;
        xs[idx] = (gr < M) ? X[(size_t)gr * K + c] : 0.f;
    }
    __syncthreads();

    float out[32];
#pragma unroll
    for (int r = 0; r < 32; r++) out[r] = 0.f;

#pragma unroll 4
    for (int k = 0; k < K; k++) {
        float w = __ldg(&W[k * 256 + col]);
#pragma unroll
        for (int r = 0; r < 32; r++)
            out[r] = fmaf(xs[r * K + k], w, out[r]);
    }

    bool even = (col & 1) == 0;
#pragma unroll 4
    for (int r = 0; r < 32; r++) {
        int gr = row0 + r;
        float other = __shfl_xor_sync(0xffffffffu, out[r], 1);
        if (gr < M) {
            g_h[(size_t)gr * 256 + col] = out[r];
            if (even) {
                __half2 hv = __floats2half2_rn(out[r], other);
                *(__half2*)(g_hh + (size_t)gr * 256 + col) = hv;
            }
        }
    }
}

// ---------------------------------------------------------------------------
// Per-node attention coefficients from fp32 h.  One warp per node.
// ---------------------------------------------------------------------------
__global__ void __launch_bounds__(256) attn_kernel(const float* __restrict__ att_src,
                                                   const float* __restrict__ att_dst, int Nn) {
    int warp = (blockIdx.x * blockDim.x + threadIdx.x) >> 5;
    int lane = threadIdx.x & 31;
    if (warp >= Nn) return;
    const float* hr = g_h + (size_t)warp * 256;
#pragma unroll
    for (int hh = 0; hh < 4; hh++) {
        float v0 = hr[hh * 64 + lane];
        float v1 = hr[hh * 64 + 32 + lane];
        float ps = v0 * att_src[hh * 64 + lane] + v1 * att_src[hh * 64 + 32 + lane];
        float pd = v0 * att_dst[hh * 64 + lane] + v1 * att_dst[hh * 64 + 32 + lane];
#pragma unroll
        for (int off = 16; off; off >>= 1) {
            ps += __shfl_xor_sync(0xffffffffu, ps, off);
            pd += __shfl_xor_sync(0xffffffffu, pd, off);
        }
        if (lane == 0) {
            g_a[(size_t)warp * 8 + hh]     = ps;
            g_a[(size_t)warp * 8 + 4 + hh] = pd;
        }
    }
}

// ---------------------------- CSR build ------------------------------------
__global__ void zero_kernel(int Nn) {
    int t = blockIdx.x * blockDim.x + threadIdx.x;
    if (t < Nn) { g_counts[t] = 0; g_cursor[t] = 0; }
    if (t == 0) g_total = 0;
}

__global__ void count_kernel(const void* __restrict__ ei, int E, int Nn) {
    int t = blockIdx.x * blockDim.x + threadIdx.x;
    if (t >= E + Nn) return;
    int d = (t < E) ? edge_at(ei, (long long)E + t) : (t - E);
    atomicAdd(&g_counts[d], 1);
}

// Warp shfl-scan + one atomicAdd per warp; slot order run-varying (fine).
__global__ void offsets_kernel(int Nn) {
    int t    = blockIdx.x * blockDim.x + threadIdx.x;
    int lane = threadIdx.x & 31;
    int c    = (t < Nn) ? g_counts[t] : 0;
    int incl = c;
#pragma unroll
    for (int off = 1; off < 32; off <<= 1) {
        int v = __shfl_up_sync(0xffffffffu, incl, off);
        if (lane >= off) incl += v;
    }
    int tot = __shfl_sync(0xffffffffu, incl, 31);
    int base = 0;
    if (lane == 31) base = atomicAdd(&g_total, tot);
    base = __shfl_sync(0xffffffffu, base, 31);
    if (t < Nn) g_off[t] = base + incl - c;
}

__global__ void scatter_kernel(const void* __restrict__ ei, int E, int Nn) {
    int t = blockIdx.x * blockDim.x + threadIdx.x;
    if (t >= E + Nn) return;
    int s, d;
    if (t < E) { s = edge_at(ei, t); d = edge_at(ei, (long long)E + t); }
    else       { s = d = t - E; }
    int pos = atomicAdd(&g_cursor[d], 1);
    g_csrc[g_off[d] + pos] = s;
}

// ---------------------------------------------------------------------------
// GAT aggregation, single pass, fp16 gather.
// One warp per destination node.  Lane l covers cols [8l, 8l+8) => head
// h = l>>3, sub = l&7.  One LDG.128 (8 halves) per lane per edge, one exp
// per lane per edge.  Head mean via shfl_xor(8)+shfl_xor(16); lanes 0-7
// store the final 64-col row as 2x float4.
// ---------------------------------------------------------------------------
template <bool RELU, bool TO_Y>
__global__ void __launch_bounds__(256) gat_aggregate(const float* __restrict__ bias,
                                                     float* __restrict__ outp, int Nn) {
    int warp = (blockIdx.x * blockDim.x + threadIdx.x) >> 5;
    int lane = threadIdx.x & 31;
    if (warp >= Nn) return;
    int n    = warp;
    int beg  = g_off[n];
    int cnt  = g_counts[n];
    int h    = lane >> 3;
    int sub  = lane & 7;

    float adv = g_a[(size_t)n * 8 + 4 + h];

    float acc[8];
#pragma unroll
    for (int i = 0; i < 8; i++) acc[i] = 0.f;
    float sw = 0.f;

    for (int j = 0; j < cnt; j++) {
        int s = g_csrc[beg + j];                      // warp-uniform broadcast
        float e = __ldg(g_a + (size_t)s * 8 + h) + adv;
        e = (e > 0.f) ? e : 0.2f * e;
        float w = __expf(e);
        sw += w;

        float4 raw = *((const float4*)(g_hh + (size_t)s * 256) + lane);
        const __half2* hp = (const __half2*)&raw;
        float2 f0 = __half22float2(hp[0]);
        float2 f1 = __half22float2(hp[1]);
        float2 f2 = __half22float2(hp[2]);
        float2 f3 = __half22float2(hp[3]);
        acc[0] = fmaf(w, f0.x, acc[0]); acc[1] = fmaf(w, f0.y, acc[1]);
        acc[2] = fmaf(w, f1.x, acc[2]); acc[3] = fmaf(w, f1.y, acc[3]);
        acc[4] = fmaf(w, f2.x, acc[4]); acc[5] = fmaf(w, f2.y, acc[5]);
        acc[6] = fmaf(w, f3.x, acc[6]); acc[7] = fmaf(w, f3.y, acc[7]);
    }

    float r = 1.f / (sw + 1e-16f);
#pragma unroll
    for (int i = 0; i < 8; i++) {
        acc[i] *= r;                                   // per-head normalize
        acc[i] += __shfl_xor_sync(0xffffffffu, acc[i], 8);
        acc[i] += __shfl_xor_sync(0xffffffffu, acc[i], 16);
    }

    if (h == 0) {   // lanes 0..7 hold 4-head sums for cols [8*sub, 8*sub+8)
        int c0 = sub * 8;
        float4 b0 = *(const float4*)(bias + c0);
        float4 b1 = *(const float4*)(bias + c0 + 4);
        float4 o0, o1;
        o0.x = 0.25f * acc[0] + b0.x;  o0.y = 0.25f * acc[1] + b0.y;
        o0.z = 0.25f * acc[2] + b0.z;  o0.w = 0.25f * acc[3] + b0.w;
        o1.x = 0.25f * acc[4] + b1.x;  o1.y = 0.25f * acc[5] + b1.y;
        o1.z = 0.25f * acc[6] + b1.z;  o1.w = 0.25f * acc[7] + b1.w;
        if (RELU) {
            o0.x = fmaxf(o0.x, 0.f); o0.y = fmaxf(o0.y, 0.f);
            o0.z = fmaxf(o0.z, 0.f); o0.w = fmaxf(o0.w, 0.f);
            o1.x = fmaxf(o1.x, 0.f); o1.y = fmaxf(o1.y, 0.f);
            o1.z = fmaxf(o1.z, 0.f); o1.w = fmaxf(o1.w, 0.f);
        }
        float* out = TO_Y ? g_y : outp;
        *(float4*)(out + (size_t)n * 64 + c0)     = o0;
        *(float4*)(out + (size_t)n * 64 + c0 + 4) = o1;
    }
}

// ---------------------------------------------------------------------------
extern "C" void kernel_launch(void* const* d_in, const int* in_sizes, int n_in,
                              void* d_out, int out_size) {
    const float* x   = (const float*)d_in[0];
    const void*  ei  = d_in[1];
    const float* W1  = (const float*)d_in[2];
    const float* as1 = (const float*)d_in[3];
    const float* ad1 = (const float*)d_in[4];
    const float* b1  = (const float*)d_in[5];
    const float* W2  = (const float*)d_in[6];
    const float* as2 = (const float*)d_in[7];
    const float* ad2 = (const float*)d_in[8];
    const float* b2  = (const float*)d_in[9];

    int N  = in_sizes[0] / 128;
    int E  = in_sizes[1] / 2;
    int EA = E + N;

    // ---- edge dtype detection + CSR build (same graph for both layers) ----
    detect_kernel<<<1, 1>>>(ei, N, E);
    zero_kernel<<<(N + 255) / 256, 256>>>(N);
    count_kernel<<<(EA + 255) / 256, 256>>>(ei, E, N);
    offsets_kernel<<<(N + 255) / 256, 256>>>(N);
    scatter_kernel<<<(EA + 255) / 256, 256>>>(ei, E, N);

    int nodeWarpBlocks = (N + 7) / 8;   // 256 thr = 8 warps/block

    // ---- layer 1 ----
    gemm_kernel<128, false><<<(N + 31) / 32, 256>>>(x, W1, N);
    attn_kernel<<<nodeWarpBlocks, 256>>>(as1, ad1, N);
    gat_aggregate<true, true><<<nodeWarpBlocks, 256>>>(b1, nullptr, N);

    // ---- layer 2 ----
    gemm_kernel<64, true><<<(N + 31) / 32, 256>>>(nullptr, W2, N);
    attn_kernel<<<nodeWarpBlocks, 256>>>(as2, ad2, N);
    gat_aggregate<false, false><<<nodeWarpBlocks, 256>>>(b2, (float*)d_out, N);
}

// round 8
// speedup vs baseline: 2.3575x; 1.7919x over previous
#include <cuda_runtime.h>
#include <cuda_fp16.h>
#include <mma.h>

using namespace nvcuda;

// Problem constants (fixed by the dataset)
#define NN 50000
#define NPAD 50048              // 782 * 64 (wmma M-tile padding)
#define EE 800000
#define EAX (EE + NN)           // edges + self loops

// ---------------- scratch (device globals; no allocations allowed) ----------
__device__ float  g_h[(size_t)NPAD * 256];   // fp32 features (attn reads; wmma writes)
__device__ __half g_hh[(size_t)NPAD * 256];  // fp16 features (aggregate reads; attn writes)
__device__ float  g_y[(size_t)NN * 64];      // layer-1 output fp32
__device__ __half g_yh[(size_t)NPAD * 64];   // layer-1 output fp16 (GEMM2 A)
__device__ __half g_xh[(size_t)NPAD * 128];  // x fp16 (GEMM1 A)
__device__ __half g_W1h[128 * 256];
__device__ __half g_W2h[64 * 256];
__device__ float  g_a[(size_t)NN * 8];       // [0..3]=a_src, [4..7]=a_dst per head
__device__ int    g_counts[NN];
__device__ int    g_cursor[NN];
__device__ int    g_off[NN];
__device__ int    g_csrc[EAX];
__device__ int    g_total;
__device__ int    g_is64;

// ---------------------------------------------------------------------------
__global__ void detect_kernel(const void* __restrict__ ei, int Nn, int E) {
    if (threadIdx.x != 0 || blockIdx.x != 0) return;
    const long long* p = (const long long*)ei;
    int ns = (E < 256) ? E : 256;
    int ok64 = 1;
    for (int i = 0; i < ns; i++) {
        long long v = p[i];
        if (v < 0 || v >= (long long)Nn) { ok64 = 0; break; }
    }
    g_is64 = ok64;
}

__device__ __forceinline__ int edge_at(const void* ei, long long idx) {
    return g_is64 ? (int)((const long long*)ei)[idx]
                  : ((const int*)ei)[idx];
}

// ---------------- fp16 conversions -----------------------------------------
__global__ void convert_x_kernel(const float* __restrict__ x, int n) {
    int t = blockIdx.x * blockDim.x + threadIdx.x;
    int stride = gridDim.x * blockDim.x;
    for (int i = t; i < n; i += stride) {
        float2 v = *(const float2*)(x + (size_t)i * 2);
        *(__half2*)(g_xh + (size_t)i * 2) = __floats2half2_rn(v.x, v.y);
    }
}

__global__ void convert_w_kernel(const float* __restrict__ W1,
                                 const float* __restrict__ W2) {
    int t = blockIdx.x * blockDim.x + threadIdx.x;
    if (t < 128 * 256) g_W1h[t] = __float2half(W1[t]);
    if (t < 64 * 256)  g_W2h[t] = __float2half(W2[t]);
}

// ---------------------------------------------------------------------------
// wmma GEMM: A[M,K] fp16 row-major @ W[K,256] fp16 row-major -> g_h fp32.
// LAYER=1: A=g_xh (K=128), W=g_W1h.  LAYER=2: A=g_yh (K=64), W=g_W2h.
// Block: 256 threads / 8 warps; tile 64 rows x 128 cols;
// warp (wid&3) -> 16-row slab, (wid>>2) -> 64-col slab (4 fragments).
// ---------------------------------------------------------------------------
template <int LAYER>
__global__ void __launch_bounds__(256) wmma_gemm() {
    constexpr int K = (LAYER == 1) ? 128 : 64;
    const __half* A  = (LAYER == 1) ? g_xh  : g_yh;
    const __half* Wh = (LAYER == 1) ? g_W1h : g_W2h;

    int wid  = threadIdx.x >> 5;
    int row0 = blockIdx.x * 64 + (wid & 3) * 16;
    int col0 = blockIdx.y * 128 + (wid >> 2) * 64;

    wmma::fragment<wmma::accumulator, 16, 16, 16, float> c[4];
#pragma unroll
    for (int i = 0; i < 4; i++) wmma::fill_fragment(c[i], 0.f);

#pragma unroll
    for (int k = 0; k < K; k += 16) {
        wmma::fragment<wmma::matrix_a, 16, 16, 16, __half, wmma::row_major> a;
        wmma::load_matrix_sync(a, A + (size_t)row0 * K + k, K);
#pragma unroll
        for (int i = 0; i < 4; i++) {
            wmma::fragment<wmma::matrix_b, 16, 16, 16, __half, wmma::row_major> b;
            wmma::load_matrix_sync(b, Wh + (size_t)k * 256 + col0 + i * 16, 256);
            wmma::mma_sync(c[i], a, b, c[i]);
        }
    }
#pragma unroll
    for (int i = 0; i < 4; i++)
        wmma::store_matrix_sync(g_h + (size_t)row0 * 256 + col0 + i * 16, c[i],
                                256, wmma::mem_row_major);
}

// ---------------------------------------------------------------------------
// Attention coefficients from fp32 h; also emits fp16 shadow g_hh.
// One warp per node.
// ---------------------------------------------------------------------------
__global__ void __launch_bounds__(256) attn_kernel(const float* __restrict__ att_src,
                                                   const float* __restrict__ att_dst, int Nn) {
    int warp = (blockIdx.x * blockDim.x + threadIdx.x) >> 5;
    int lane = threadIdx.x & 31;
    if (warp >= Nn) return;
    const float* hr = g_h + (size_t)warp * 256;
    __half* hw = g_hh + (size_t)warp * 256;
#pragma unroll
    for (int hh = 0; hh < 4; hh++) {
        float v0 = hr[hh * 64 + lane];
        float v1 = hr[hh * 64 + 32 + lane];
        hw[hh * 64 + lane]      = __float2half(v0);
        hw[hh * 64 + 32 + lane] = __float2half(v1);
        float ps = v0 * att_src[hh * 64 + lane] + v1 * att_src[hh * 64 + 32 + lane];
        float pd = v0 * att_dst[hh * 64 + lane] + v1 * att_dst[hh * 64 + 32 + lane];
#pragma unroll
        for (int off = 16; off; off >>= 1) {
            ps += __shfl_xor_sync(0xffffffffu, ps, off);
            pd += __shfl_xor_sync(0xffffffffu, pd, off);
        }
        if (lane == 0) {
            g_a[(size_t)warp * 8 + hh]     = ps;
            g_a[(size_t)warp * 8 + 4 + hh] = pd;
        }
    }
}

// ---------------------------- CSR build ------------------------------------
__global__ void zero_kernel(int Nn) {
    int t = blockIdx.x * blockDim.x + threadIdx.x;
    if (t < Nn) { g_counts[t] = 0; g_cursor[t] = 0; }
    if (t == 0) g_total = 0;
}

__global__ void count_kernel(const void* __restrict__ ei, int E, int Nn) {
    int t = blockIdx.x * blockDim.x + threadIdx.x;
    if (t >= E + Nn) return;
    int d = (t < E) ? edge_at(ei, (long long)E + t) : (t - E);
    atomicAdd(&g_counts[d], 1);
}

__global__ void offsets_kernel(int Nn) {
    int t    = blockIdx.x * blockDim.x + threadIdx.x;
    int lane = threadIdx.x & 31;
    int c    = (t < Nn) ? g_counts[t] : 0;
    int incl = c;
#pragma unroll
    for (int off = 1; off < 32; off <<= 1) {
        int v = __shfl_up_sync(0xffffffffu, incl, off);
        if (lane >= off) incl += v;
    }
    int tot = __shfl_sync(0xffffffffu, incl, 31);
    int base = 0;
    if (lane == 31) base = atomicAdd(&g_total, tot);
    base = __shfl_sync(0xffffffffu, base, 31);
    if (t < Nn) g_off[t] = base + incl - c;
}

__global__ void scatter_kernel(const void* __restrict__ ei, int E, int Nn) {
    int t = blockIdx.x * blockDim.x + threadIdx.x;
    if (t >= E + Nn) return;
    int s, d;
    if (t < E) { s = edge_at(ei, t); d = edge_at(ei, (long long)E + t); }
    else       { s = d = t - E; }
    int pos = atomicAdd(&g_cursor[d], 1);
    g_csrc[g_off[d] + pos] = s;
}

// ---------------------------------------------------------------------------
// GAT aggregation, single pass, fp16 gather, x2 unrolled (gather MLP=2).
// One warp per destination node; lane l covers cols [8l, 8l+8), head = l>>3.
// ---------------------------------------------------------------------------
template <bool RELU, bool TO_Y>
__global__ void __launch_bounds__(256) gat_aggregate(const float* __restrict__ bias,
                                                     float* __restrict__ outp, int Nn) {
    int warp = (blockIdx.x * blockDim.x + threadIdx.x) >> 5;
    int lane = threadIdx.x & 31;
    if (warp >= Nn) return;
    int n    = warp;
    int beg  = g_off[n];
    int cnt  = g_counts[n];
    int h    = lane >> 3;
    int sub  = lane & 7;

    float adv = g_a[(size_t)n * 8 + 4 + h];

    float acc[8];
#pragma unroll
    for (int i = 0; i < 8; i++) acc[i] = 0.f;
    float sw = 0.f;

    int j = 0;
    for (; j + 2 <= cnt; j += 2) {
        int s0 = g_csrc[beg + j];
        int s1 = g_csrc[beg + j + 1];
        float e0 = __ldg(g_a + (size_t)s0 * 8 + h) + adv;
        float e1 = __ldg(g_a + (size_t)s1 * 8 + h) + adv;
        float4 r0 = *((const float4*)(g_hh + (size_t)s0 * 256) + lane);
        float4 r1 = *((const float4*)(g_hh + (size_t)s1 * 256) + lane);
        e0 = (e0 > 0.f) ? e0 : 0.2f * e0;
        e1 = (e1 > 0.f) ? e1 : 0.2f * e1;
        float w0 = __expf(e0), w1 = __expf(e1);
        sw += w0 + w1;
        {
            const __half2* hp = (const __half2*)&r0;
            float2 f0 = __half22float2(hp[0]), f1 = __half22float2(hp[1]);
            float2 f2 = __half22float2(hp[2]), f3 = __half22float2(hp[3]);
            acc[0] = fmaf(w0, f0.x, acc[0]); acc[1] = fmaf(w0, f0.y, acc[1]);
            acc[2] = fmaf(w0, f1.x, acc[2]); acc[3] = fmaf(w0, f1.y, acc[3]);
            acc[4] = fmaf(w0, f2.x, acc[4]); acc[5] = fmaf(w0, f2.y, acc[5]);
            acc[6] = fmaf(w0, f3.x, acc[6]); acc[7] = fmaf(w0, f3.y, acc[7]);
        }
        {
            const __half2* hp = (const __half2*)&r1;
            float2 f0 = __half22float2(hp[0]), f1 = __half22float2(hp[1]);
            float2 f2 = __half22float2(hp[2]), f3 = __half22float2(hp[3]);
            acc[0] = fmaf(w1, f0.x, acc[0]); acc[1] = fmaf(w1, f0.y, acc[1]);
            acc[2] = fmaf(w1, f1.x, acc[2]); acc[3] = fmaf(w1, f1.y, acc[3]);
            acc[4] = fmaf(w1, f2.x, acc[4]); acc[5] = fmaf(w1, f2.y, acc[5]);
            acc[6] = fmaf(w1, f3.x, acc[6]); acc[7] = fmaf(w1, f3.y, acc[7]);
        }
    }
    if (j < cnt) {
        int s = g_csrc[beg + j];
        float e = __ldg(g_a + (size_t)s * 8 + h) + adv;
        e = (e > 0.f) ? e : 0.2f * e;
        float w = __expf(e);
        sw += w;
        float4 raw = *((const float4*)(g_hh + (size_t)s * 256) + lane);
        const __half2* hp = (const __half2*)&raw;
        float2 f0 = __half22float2(hp[0]), f1 = __half22float2(hp[1]);
        float2 f2 = __half22float2(hp[2]), f3 = __half22float2(hp[3]);
        acc[0] = fmaf(w, f0.x, acc[0]); acc[1] = fmaf(w, f0.y, acc[1]);
        acc[2] = fmaf(w, f1.x, acc[2]); acc[3] = fmaf(w, f1.y, acc[3]);
        acc[4] = fmaf(w, f2.x, acc[4]); acc[5] = fmaf(w, f2.y, acc[5]);
        acc[6] = fmaf(w, f3.x, acc[6]); acc[7] = fmaf(w, f3.y, acc[7]);
    }

    float r = 1.f / (sw + 1e-16f);
#pragma unroll
    for (int i = 0; i < 8; i++) {
        acc[i] *= r;
        acc[i] += __shfl_xor_sync(0xffffffffu, acc[i], 8);
        acc[i] += __shfl_xor_sync(0xffffffffu, acc[i], 16);
    }

    if (h == 0) {   // lanes 0..7: 4-head sums for cols [8*sub, 8*sub+8)
        int c0 = sub * 8;
        float4 b0 = *(const float4*)(bias + c0);
        float4 b1 = *(const float4*)(bias + c0 + 4);
        float4 o0, o1;
        o0.x = 0.25f * acc[0] + b0.x;  o0.y = 0.25f * acc[1] + b0.y;
        o0.z = 0.25f * acc[2] + b0.z;  o0.w = 0.25f * acc[3] + b0.w;
        o1.x = 0.25f * acc[4] + b1.x;  o1.y = 0.25f * acc[5] + b1.y;
        o1.z = 0.25f * acc[6] + b1.z;  o1.w = 0.25f * acc[7] + b1.w;
        if (RELU) {
            o0.x = fmaxf(o0.x, 0.f); o0.y = fmaxf(o0.y, 0.f);
            o0.z = fmaxf(o0.z, 0.f); o0.w = fmaxf(o0.w, 0.f);
            o1.x = fmaxf(o1.x, 0.f); o1.y = fmaxf(o1.y, 0.f);
            o1.z = fmaxf(o1.z, 0.f); o1.w = fmaxf(o1.w, 0.f);
        }
        float* out = TO_Y ? g_y : outp;
        *(float4*)(out + (size_t)n * 64 + c0)     = o0;
        *(float4*)(out + (size_t)n * 64 + c0 + 4) = o1;
        if (TO_Y) {  // fp16 shadow for GEMM2's A operand
            __half2* yh = (__half2*)(g_yh + (size_t)n * 64 + c0);
            yh[0] = __floats2half2_rn(o0.x, o0.y);
            yh[1] = __floats2half2_rn(o0.z, o0.w);
            yh[2] = __floats2half2_rn(o1.x, o1.y);
            yh[3] = __floats2half2_rn(o1.z, o1.w);
        }
    }
}

// ---------------------------------------------------------------------------
extern "C" void kernel_launch(void* const* d_in, const int* in_sizes, int n_in,
                              void* d_out, int out_size) {
    const float* x   = (const float*)d_in[0];
    const void*  ei  = d_in[1];
    const float* W1  = (const float*)d_in[2];
    const float* as1 = (const float*)d_in[3];
    const float* ad1 = (const float*)d_in[4];
    const float* b1  = (const float*)d_in[5];
    const float* W2  = (const float*)d_in[6];
    const float* as2 = (const float*)d_in[7];
    const float* ad2 = (const float*)d_in[8];
    const float* b2  = (const float*)d_in[9];

    int N  = in_sizes[0] / 128;
    int E  = in_sizes[1] / 2;
    int EA = E + N;

    // ---- dtype detection + fp16 conversions + CSR build ----
    detect_kernel<<<1, 1>>>(ei, N, E);
    convert_x_kernel<<<592, 256>>>(x, N * 64);       // N*128 floats as float2 pairs
    convert_w_kernel<<<(128 * 256 + 255) / 256, 256>>>(W1, W2);
    zero_kernel<<<(N + 255) / 256, 256>>>(N);
    count_kernel<<<(EA + 255) / 256, 256>>>(ei, E, N);
    offsets_kernel<<<(N + 255) / 256, 256>>>(N);
    scatter_kernel<<<(EA + 255) / 256, 256>>>(ei, E, N);

    int nodeWarpBlocks = (N + 7) / 8;   // 256 thr = 8 warps/block
    dim3 ggrid(NPAD / 64, 2);

    // ---- layer 1 ----
    wmma_gemm<1><<<ggrid, 256>>>();
    attn_kernel<<<nodeWarpBlocks, 256>>>(as1, ad1, N);
    gat_aggregate<true, true><<<nodeWarpBlocks, 256>>>(b1, nullptr, N);

    // ---- layer 2 ----
    wmma_gemm<2><<<ggrid, 256>>>();
    attn_kernel<<<nodeWarpBlocks, 256>>>(as2, ad2, N);
    gat_aggregate<false, false><<<nodeWarpBlocks, 256>>>(b2, (float*)d_out, N);
}